// round 10
// baseline (speedup 1.0000x reference)
#include <cuda_runtime.h>
#include <cuda_fp16.h>
#include <cstdint>
#include <math.h>

// ============================================================================
// Experts MLP via plain fp16 mma.sync GEMMs (fp32 accumulate).
// R10: CTA tile 128x256, warp 64x64, 4-stage cp.async, ONE barrier per TWO
// k64 chunks (stage-half ping-pong), fills issued early in each pair.
// ============================================================================

#define E_ 8
#define T_ 4096
#define D_ 1024
#define H_ 2048

#define A_BYTES 16384              // 128 rows * 128B
#define STAGE   49152              // A(16K) + B(32K)
#define NSTAGE  4

__device__ __align__(256) __half g_x2[(size_t)32768 * 1024];
__device__ __align__(256) __half g_w1t[(size_t)8 * 2048 * 1024];
__device__ __align__(256) __half g_h2[(size_t)32768 * 2048];
__device__ __align__(256) __half g_w2t[(size_t)8 * 1024 * 2048];

__device__ __forceinline__ uint32_t smem_u32(const void* p) {
    uint32_t a;
    asm("{ .reg .u64 t; cvta.to.shared.u64 t, %1; cvt.u32.u64 %0, t; }"
        : "=r"(a) : "l"(p));
    return a;
}
__device__ __forceinline__ void cpa16(uint32_t dst, const void* src) {
    asm volatile("cp.async.cg.shared.global [%0], [%1], 16;" :: "r"(dst), "l"(src));
}
__device__ __forceinline__ void ldsm_x4(uint32_t* r, uint32_t addr) {
    asm volatile("ldmatrix.sync.aligned.m8n8.x4.shared.b16 {%0,%1,%2,%3}, [%4];"
                 : "=r"(r[0]), "=r"(r[1]), "=r"(r[2]), "=r"(r[3]) : "r"(addr));
}
__device__ __forceinline__ void mma_f16(float* c, const uint32_t* a,
                                        uint32_t b0, uint32_t b1) {
    asm volatile(
        "mma.sync.aligned.m16n8k16.row.col.f32.f16.f16.f32 "
        "{%0,%1,%2,%3}, {%4,%5,%6,%7}, {%8,%9}, {%0,%1,%2,%3};"
        : "+f"(c[0]), "+f"(c[1]), "+f"(c[2]), "+f"(c[3])
        : "r"(a[0]), "r"(a[1]), "r"(a[2]), "r"(a[3]), "r"(b0), "r"(b1));
}

__device__ __forceinline__ float gelu_exact(float x) {
    return 0.5f * x * (1.0f + erff(x * 0.70710678118654752f));
}
__device__ __forceinline__ uint32_t pk(__half a, __half b) {
    return (uint32_t)__half_as_ushort(a) | ((uint32_t)__half_as_ushort(b) << 16);
}

// ============================================================================
// prepasses
// ============================================================================
__global__ void convert_x(const float* __restrict__ x, __half* __restrict__ x2) {
    size_t base = ((size_t)blockIdx.x * 256 + threadIdx.x) * 4;
    float4 v = *(const float4*)(x + base);
    uint2 o = make_uint2(pk(__float2half_rn(v.x), __float2half_rn(v.y)),
                         pk(__float2half_rn(v.z), __float2half_rn(v.w)));
    *(uint2*)(x2 + base) = o;
}

__global__ void convert_w(const float* __restrict__ w, __half* __restrict__ wt,
                          int K, int N) {
    __shared__ float t[32][33];
    const int e = blockIdx.z;
    const int nb = blockIdx.x * 32, kb = blockIdx.y * 32;
    const float* we = w + (size_t)e * K * N;
    __half* oe = wt + (size_t)e * N * K;
    const int tx = threadIdx.x, ty = threadIdx.y; // (32, 8)
    #pragma unroll
    for (int i = 0; i < 4; i++)
        t[ty + 8 * i][tx] = we[(size_t)(kb + ty + 8 * i) * N + nb + tx];
    __syncthreads();
    #pragma unroll
    for (int i = 0; i < 4; i++) {
        int n = nb + ty + 8 * i, k = kb + tx;
        oe[(size_t)n * K + k] = __float2half_rn(t[tx][ty + 8 * i]);
    }
}

// ============================================================================
// GEMM: C tile 128x256, warp 64x64, k64 chunks, 4 stages, sync per 2 chunks.
// ============================================================================
template <int EPI, int KR>
__global__ __launch_bounds__(256, 1)
void gemm_mma(const __half* __restrict__ A,
              const __half* __restrict__ B,
              const float* __restrict__ bias,
              float* __restrict__ OutF,
              __half* __restrict__ OutH,
              int NBtot)
{
    extern __shared__ __align__(1024) char sm[];
    __shared__ float s_bias[256];

    constexpr int NC = KR / 64;                    // k64 chunks
    constexpr int NP = NC / 2;                     // chunk pairs
    constexpr size_t gStride = (size_t)64 * KR;    // bytes between seg rows

    const int tid = threadIdx.x;
    const int wid = tid >> 5;
    const int lid = tid & 31;
    const int warp_m = wid >> 2;
    const int warp_n = wid & 3;
    const int e = blockIdx.z;
    const int rowBase = blockIdx.y * 128;
    const int colBase = blockIdx.x * 256;
    const size_t rowGlob0 = (size_t)e * T_ + rowBase;
    const uint32_t smb = smem_u32(sm);

    s_bias[tid] = bias[(size_t)e * NBtot + colBase + tid];

    // cp.async: A 1024 segs (4/thr), B 2048 segs (8/thr)
    const int r0 = tid >> 3, g0 = tid & 7;
    const char* aCur = (const char*)(A + (rowGlob0 + r0) * (size_t)KR) + g0 * 16;
    const char* bCur = (const char*)(B + ((size_t)e * NBtot + colBase + r0) * (size_t)KR) + g0 * 16;
    const uint32_t sO0 = (uint32_t)(r0 * 128 + ((g0 << 4) ^ ((r0 & 7) << 4)));

    // ldmatrix addressing
    const int lr = (lid & 7) + ((lid >> 3) & 1) * 8;
    const uint32_t lcol = ((lid >> 4) & 1) << 4;
    const uint32_t xr = (uint32_t)(lr & 7) << 4;
    const uint32_t arb0 = (uint32_t)(warp_m * 64 + lr) * 128;
    const uint32_t brb0 = (uint32_t)(warp_n * 64 + lr) * 128 + A_BYTES;

    uint32_t colq[4];
    #pragma unroll
    for (int q = 0; q < 4; q++) colq[q] = ((uint32_t)(q << 5) | lcol) ^ xr;

    float acc[4][8][4];
    #pragma unroll
    for (int m = 0; m < 4; m++)
        #pragma unroll
        for (int n = 0; n < 8; n++)
            #pragma unroll
            for (int q = 0; q < 4; q++)
                acc[m][n][q] = 0.0f;

    auto fill = [&](uint32_t sbase) {
        uint32_t sb = sbase + sO0;
        #pragma unroll
        for (int i = 0; i < 4; i++)
            cpa16(sb + i * 4096, aCur + i * gStride);
        #pragma unroll
        for (int i = 0; i < 8; i++)
            cpa16(sb + A_BYTES + i * 4096, bCur + i * gStride);
        asm volatile("cp.async.commit_group;" ::: "memory");
        aCur += 128; bCur += 128;
    };
    auto commit_empty = [&]() {
        asm volatile("cp.async.commit_group;" ::: "memory");
    };

    auto ldA = [&](uint32_t st, uint32_t col, uint32_t (&fr)[4][4]) {
        #pragma unroll
        for (int f = 0; f < 4; f++)
            ldsm_x4(fr[f], st + arb0 + f * 2048 + col);
    };
    auto ldB = [&](uint32_t st, uint32_t col, uint32_t (&fr)[4][4]) {
        #pragma unroll
        for (int g = 0; g < 4; g++)
            ldsm_x4(fr[g], st + brb0 + g * 2048 + col);
    };
    auto mmaT = [&](const uint32_t (&a)[4][4], const uint32_t (&b)[4][4]) {
        #pragma unroll
        for (int m = 0; m < 4; m++)
            #pragma unroll
            for (int n = 0; n < 8; n++)
                mma_f16(acc[m][n], a[m], b[n >> 1][n & 1], b[n >> 1][2 + (n & 1)]);
    };

    // stage bases
    const uint32_t stg[4] = { smb, smb + STAGE, smb + 2 * STAGE, smb + 3 * STAGE };

    // prologue: fill pair 0 (chunks 0,1)
    fill(stg[0]);
    fill(stg[1]);
    asm volatile("cp.async.wait_group 0;" ::: "memory");
    __syncthreads();

    uint32_t aF[2][4][4], bF[2][4][4];
    ldA(stg[0], colq[0], aF[0]);
    ldB(stg[0], colq[0], bF[0]);

    #pragma unroll 1
    for (int p = 0; p < NP; p++) {
        const uint32_t sa = stg[(p & 1) ? 2 : 0];
        const uint32_t sb2 = sa + STAGE;
        const uint32_t sc = stg[(p & 1) ? 0 : 2];
        const uint32_t sd = sc + STAGE;
        const int c0 = 2 * p;

        // ---- chunk c0 (stage sa); fills for pair p+1 issued here ----
        ldA(sa, colq[1], aF[1]);
        ldB(sa, colq[1], bF[1]);
        if (c0 + 2 < NC) fill(sc); else commit_empty();
        mmaT(aF[0], bF[0]);                // q0

        ldA(sa, colq[2], aF[0]);
        ldB(sa, colq[2], bF[0]);
        if (c0 + 3 < NC) fill(sd); else commit_empty();
        mmaT(aF[1], bF[1]);                // q1

        ldA(sa, colq[3], aF[1]);
        ldB(sa, colq[3], bF[1]);
        mmaT(aF[0], bF[0]);                // q2

        ldA(sb2, colq[0], aF[0]);          // chunk c0+1 q0 (resident)
        ldB(sb2, colq[0], bF[0]);
        mmaT(aF[1], bF[1]);                // q3

        // ---- chunk c0+1 (stage sb2) ----
        ldA(sb2, colq[1], aF[1]);
        ldB(sb2, colq[1], bF[1]);
        mmaT(aF[0], bF[0]);                // q0'

        ldA(sb2, colq[2], aF[0]);
        ldB(sb2, colq[2], bF[0]);
        mmaT(aF[1], bF[1]);                // q1'

        ldA(sb2, colq[3], aF[1]);
        ldB(sb2, colq[3], bF[1]);
        mmaT(aF[0], bF[0]);                // q2'

        asm volatile("cp.async.wait_group 0;" ::: "memory");
        __syncthreads();
        if (p + 1 < NP) ldA(sc, colq[0], aF[0]);   // next pair q0 prefetch
        mmaT(aF[1], bF[1]);                // q3' (register-only, hides barrier)
        if (p + 1 < NP) ldB(sc, colq[0], bF[0]);
    }
    __syncthreads();

    // ---- epilogue ----
    #pragma unroll
    for (int m = 0; m < 4; m++) {
        const size_t rG = rowGlob0 + warp_m * 64 + m * 16 + (lid >> 2);
        #pragma unroll
        for (int n = 0; n < 8; n++) {
            const int cl = warp_n * 64 + n * 8 + (lid & 3) * 2;
            const float b0 = s_bias[cl], b1 = s_bias[cl + 1];
            const int cg = colBase + cl;
            #pragma unroll
            for (int h = 0; h < 2; h++) {
                float v0 = acc[m][n][2 * h + 0] + b0;
                float v1 = acc[m][n][2 * h + 1] + b1;
                const size_t rr = rG + h * 8;
                if (EPI == 1) {
                    v0 = gelu_exact(v0); v1 = gelu_exact(v1);
                    *(uint32_t*)(OutH + rr * (size_t)NBtot + cg) =
                        pk(__float2half_rn(v0), __float2half_rn(v1));
                } else {
                    *(float2*)(OutF + rr * (size_t)NBtot + cg) = make_float2(v0, v1);
                }
            }
        }
    }
}

// ============================================================================
extern "C" void kernel_launch(void* const* d_in, const int* in_sizes, int n_in,
                              void* d_out, int out_size)
{
    (void)in_sizes; (void)n_in; (void)out_size;
    const float* x  = (const float*)d_in[0];
    const float* w1 = (const float*)d_in[1];
    const float* b1 = (const float*)d_in[2];
    const float* w2 = (const float*)d_in[3];
    const float* b2 = (const float*)d_in[4];
    float* out = (float*)d_out;

    __half *x2, *w1t, *h2, *w2t;
    cudaGetSymbolAddress((void**)&x2,  g_x2);
    cudaGetSymbolAddress((void**)&w1t, g_w1t);
    cudaGetSymbolAddress((void**)&h2,  g_h2);
    cudaGetSymbolAddress((void**)&w2t, g_w2t);

    const int SMEM = NSTAGE * STAGE;   // 196608
    cudaFuncSetAttribute((const void*)gemm_mma<1, D_>,
                         cudaFuncAttributeMaxDynamicSharedMemorySize, SMEM);
    cudaFuncSetAttribute((const void*)gemm_mma<0, H_>,
                         cudaFuncAttributeMaxDynamicSharedMemorySize, SMEM);

    convert_x<<<32768, 256>>>(x, x2);
    convert_w<<<dim3(H_ / 32, D_ / 32, E_), dim3(32, 8)>>>(w1, w1t, D_, H_);
    convert_w<<<dim3(D_ / 32, H_ / 32, E_), dim3(32, 8)>>>(w2, w2t, H_, D_);

    // GEMM1: K=1024, tiles 128x256 over N=2048
    gemm_mma<1, D_><<<dim3(H_ / 256, T_ / 128, E_), 256, SMEM>>>(
        x2, w1t, b1, nullptr, h2, H_);

    // GEMM2: K=2048, tiles 128x256 over N=1024
    gemm_mma<0, H_><<<dim3(D_ / 256, T_ / 128, E_), 256, SMEM>>>(
        h2, w2t, b2, out, nullptr, D_);
}